// round 13
// baseline (speedup 1.0000x reference)
#include <cuda_runtime.h>
#include <cstdint>

// ---------------------------------------------------------------------------
// B=2, N=1024, D=1024, K=8 (circulant), H=16, dh=64
// Weights expanded TRANSPOSED: Wt[n][k] = W[k][n]  (k contiguous)
// ---------------------------------------------------------------------------
constexpr int DD = 1024;
constexpr int MM = 2048;

__device__ float g_We[4][DD * DD];   // expanded weights, layout Wt[n][k]
__device__ float g_Q[MM * DD];
__device__ float g_K[MM * DD];
__device__ float g_V[MM * DD];
__device__ float g_Vt[MM * DD];      // V transposed per batch: [b][col][seq]
__device__ float g_O[MM * DD];

__device__ __forceinline__ uint32_t f2tf32(float f) {
    uint32_t r;
    asm("cvt.rna.tf32.f32 %0, %1;" : "=r"(r) : "f"(f));
    return r;
}
__device__ __forceinline__ uint32_t u2tf32(uint32_t u) {
    uint32_t r;
    asm("cvt.rna.tf32.f32 %0, %1;" : "=r"(r) : "f"(__uint_as_float(u)));
    return r;
}

#define MMA_TF32(ACC, A0, A1, A2, A3, B0, B1)                            \
    asm volatile(                                                        \
        "mma.sync.aligned.m16n8k8.row.col.f32.tf32.tf32.f32 "            \
        "{%0,%1,%2,%3}, {%4,%5,%6,%7}, {%8,%9}, {%0,%1,%2,%3};"          \
        : "+f"((ACC)[0]), "+f"((ACC)[1]), "+f"((ACC)[2]), "+f"((ACC)[3]) \
        : "r"(A0), "r"(A1), "r"(A2), "r"(A3), "r"(B0), "r"(B1))

#define LDSM4(R0, R1, R2, R3, ADDR)                                      \
    asm volatile("ldmatrix.sync.aligned.m8n8.x4.shared.b16 "             \
                 "{%0,%1,%2,%3}, [%4];"                                  \
                 : "=r"(R0), "=r"(R1), "=r"(R2), "=r"(R3) : "r"(ADDR))

__device__ __forceinline__ void cp16(uint32_t smem, const void* g) {
    asm volatile("cp.async.ca.shared.global [%0], [%1], 16;\n"
                 :: "r"(smem), "l"(g));
}

extern __shared__ uint32_t dynsm[];

// ---------------------------------------------------------------------------
// Expand circulant blocks TRANSPOSED: dst[n][k] = w[n/8][k/8][(n-k)&7]
// ---------------------------------------------------------------------------
__global__ void expand_kernel(const float* __restrict__ w0,
                              const float* __restrict__ w1,
                              const float* __restrict__ w2,
                              const float* __restrict__ w3)
{
    const float* w;
    switch (blockIdx.y) {
        case 0:  w = w0; break;
        case 1:  w = w1; break;
        case 2:  w = w2; break;
        default: w = w3; break;
    }
    float* dst = g_We[blockIdx.y];
    int idx = blockIdx.x * 256 + threadIdx.x;
    int n = idx >> 10;
    int k = idx & 1023;
    dst[idx] = w[((n >> 3) << 10) + ((k >> 3) << 3) + ((n - k) & 7)];
}

// ---------------------------------------------------------------------------
// Per-batch transpose: g_Vt[b][c][s] = g_V[b][s][c].  Tiled 32x32.
// ---------------------------------------------------------------------------
__global__ __launch_bounds__(256)
void transpose_v()
{
    __shared__ float t[32][33];
    const int b  = blockIdx.z;
    const int s0 = blockIdx.x * 32;
    const int c0 = blockIdx.y * 32;
    const float* src = g_V + (size_t)b * (1024 * 1024);
    float* dst = g_Vt + (size_t)b * (1024 * 1024);
#pragma unroll
    for (int i = 0; i < 4; i++) {
        int row = threadIdx.y + i * 8;
        t[row][threadIdx.x] = src[(size_t)(s0 + row) * 1024 + c0 + threadIdx.x];
    }
    __syncthreads();
#pragma unroll
    for (int i = 0; i < 4; i++) {
        int row = threadIdx.y + i * 8;
        dst[(size_t)(c0 + row) * 1024 + s0 + threadIdx.x] = t[threadIdx.x][row];
    }
}

// ---------------------------------------------------------------------------
// TF32 GEMM + bias: 128x128 tile, BK=16, 8 warps of 32x64, ldmatrix frags,
// 4-stage cp.async pipeline (dynamic smem, raw f32; cvt post-LDSM).
// ---------------------------------------------------------------------------
constexpr int GST  = 20;           // smem row stride (floats)
constexpr int BUFW = 128 * GST;    // words per (A or B) stage
constexpr int NST  = 4;            // pipeline stages
constexpr int GEMM_SMEM = 2 * NST * BUFW * 4;   // 81920 bytes

__global__ __launch_bounds__(256, 2)
void gemm_tf32(const float* __restrict__ A,
               const float* __restrict__ B0, const float* __restrict__ B1,
               const float* __restrict__ B2,
               const float* __restrict__ bi0, const float* __restrict__ bi1,
               const float* __restrict__ bi2,
               float* __restrict__ C0, float* __restrict__ C1,
               float* __restrict__ C2)
{
    const float* Bm; const float* bias; float* C;
    if (blockIdx.z == 0)      { Bm = B0; bias = bi0; C = C0; }
    else if (blockIdx.z == 1) { Bm = B1; bias = bi1; C = C1; }
    else                      { Bm = B2; bias = bi2; C = C2; }

    const int tid  = threadIdx.x;
    const int warp = tid >> 5;
    const int lane = tid & 31;
    const int grp  = lane >> 2;
    const int q    = lane & 3;

    const int cRow = blockIdx.y * 128;
    const int cCol = blockIdx.x * 128;
    const int wm   = (warp & 3) * 32;
    const int wn   = (warp >> 2) * 64;

    const int sr = tid >> 2;
    const int sc = (tid & 3) * 4;

    const float* Ap = A  + (size_t)(cRow + sr) * DD + sc;
    const float* Bp = Bm + (size_t)(cCol + sr) * DD + sc;

    const uint32_t aBase = (uint32_t)__cvta_generic_to_shared(dynsm);
    const uint32_t bBase = aBase + NST * BUFW * 4;

    const uint32_t sA0 = aBase + (sr * GST + sc) * 4;
    const uint32_t sA1 = sA0 + 64 * GST * 4;
    const uint32_t sB0 = bBase + (sr * GST + sc) * 4;
    const uint32_t sB1 = sB0 + 64 * GST * 4;

    uint32_t aAddr[2];
#pragma unroll
    for (int mi = 0; mi < 2; mi++)
        aAddr[mi] = aBase + ((wm + mi * 16 + (lane & 15)) * GST) * 4 +
                    (lane >> 4) * 16;
    uint32_t bAddr[4];
#pragma unroll
    for (int p = 0; p < 4; p++)
        bAddr[p] = bBase + ((wn + (2 * p + (lane >> 4)) * 8 + (lane & 7)) * GST) * 4 +
                   ((lane >> 3) & 1) * 16;

    float acc[2][8][4];
#pragma unroll
    for (int mi = 0; mi < 2; mi++)
#pragma unroll
        for (int ni = 0; ni < 8; ni++)
#pragma unroll
            for (int c = 0; c < 4; c++) acc[mi][ni][c] = 0.f;

    auto issue_stage = [&](int s, int kb) {
        const uint32_t so = (uint32_t)s * (BUFW * 4);
        cp16(sA0 + so, Ap + kb);
        cp16(sA1 + so, Ap + 64 * DD + kb);
        cp16(sB0 + so, Bp + kb);
        cp16(sB1 + so, Bp + 64 * DD + kb);
        asm volatile("cp.async.commit_group;");
    };

    auto compute = [&](int it) {
        const uint32_t so = (uint32_t)(it & 3) * (BUFW * 4);
#pragma unroll
        for (int kc = 0; kc < 2; kc++) {
            const uint32_t ko = so + kc * 32;
            uint32_t a0[4], a1[4];
            LDSM4(a0[0], a0[1], a0[2], a0[3], aAddr[0] + ko);
            LDSM4(a1[0], a1[1], a1[2], a1[3], aAddr[1] + ko);
            uint32_t bv[4][4];
#pragma unroll
            for (int p = 0; p < 4; p++)
                LDSM4(bv[p][0], bv[p][1], bv[p][2], bv[p][3], bAddr[p] + ko);
#pragma unroll
            for (int j = 0; j < 4; j++) { a0[j] = u2tf32(a0[j]); a1[j] = u2tf32(a1[j]); }
#pragma unroll
            for (int p = 0; p < 4; p++)
#pragma unroll
                for (int j = 0; j < 4; j++) bv[p][j] = u2tf32(bv[p][j]);
#pragma unroll
            for (int p = 0; p < 4; p++) {
                MMA_TF32(acc[0][2 * p],     a0[0], a0[1], a0[2], a0[3], bv[p][0], bv[p][1]);
                MMA_TF32(acc[0][2 * p + 1], a0[0], a0[1], a0[2], a0[3], bv[p][2], bv[p][3]);
                MMA_TF32(acc[1][2 * p],     a1[0], a1[1], a1[2], a1[3], bv[p][0], bv[p][1]);
                MMA_TF32(acc[1][2 * p + 1], a1[0], a1[1], a1[2], a1[3], bv[p][2], bv[p][3]);
            }
        }
    };

    issue_stage(0, 0);
    issue_stage(1, 16);
    issue_stage(2, 32);

    for (int it = 0; it <= 60; it++) {
        asm volatile("cp.async.wait_group 2;");
        __syncthreads();
        compute(it);
        __syncthreads();
        issue_stage((it + 3) & 3, (it + 3) * 16);
    }
    asm volatile("cp.async.wait_group 2;");
    __syncthreads();
    compute(61);
    asm volatile("cp.async.wait_group 1;");
    __syncthreads();
    compute(62);
    asm volatile("cp.async.wait_group 0;");
    __syncthreads();
    compute(63);

#pragma unroll
    for (int mi = 0; mi < 2; mi++) {
#pragma unroll
        for (int ni = 0; ni < 8; ni++) {
            int row = cRow + wm + mi * 16 + grp;
            int col = cCol + wn + ni * 8 + q * 2;
            float bx = bias[col], by = bias[col + 1];
            *(float2*)(C + (size_t)row * DD + col) =
                make_float2(acc[mi][ni][0] + bx, acc[mi][ni][1] + by);
            *(float2*)(C + (size_t)(row + 8) * DD + col) =
                make_float2(acc[mi][ni][2] + bx, acc[mi][ni][3] + by);
        }
    }
}

// ---------------------------------------------------------------------------
// Tensor-core causal flash attention: LDSM frags + cp.async double-buffered
// K/V staging (raw f32; cvt post-LDSM). Dynamic smem:
//   Ksm[2][64*68] then Vsm[2][64*68]  (K buf doubles as P region)
// ---------------------------------------------------------------------------
constexpr int FST  = 68;                 // row stride (words)
constexpr int FBUF = 64 * FST;           // words per buffer
constexpr int FLASH_SMEM = 4 * FBUF * 4; // 69632 bytes

__global__ __launch_bounds__(128, 3)
void flash_mma(const float* __restrict__ Qg, const float* __restrict__ Kg,
               const float* __restrict__ Vtg, float* __restrict__ Og)
{
    const int tid  = threadIdx.x;
    const int warp = tid >> 5;
    const int lane = tid & 31;
    const int grp  = lane >> 2;
    const int q    = lane & 3;

    const int qb = 15 - blockIdx.y;
    const int i0 = qb * 64;
    const int h  = blockIdx.x & 15;
    const int b  = blockIdx.x >> 4;
    const size_t base   = (size_t)b * (1024 * 1024) + h * 64;
    const size_t vtbase = (size_t)b * (1024 * 1024) + (size_t)(h * 64) * 1024;

    const int wm = warp * 16;
    const int r0 = i0 + wm + grp;

    const uint32_t kBase = (uint32_t)__cvta_generic_to_shared(dynsm);
    const uint32_t vBase = kBase + 2 * FBUF * 4;

    // staging map: each thread covers rows (tid>>4)+it*8, cols (tid&15)*4
    const int srow = tid >> 4;
    const int sc4  = (tid & 15) << 2;
    const uint32_t stOff = (srow * FST + sc4) * 4;

    // ldmatrix lane addresses (buffer 0 offsets)
    uint32_t kAddr[4], vAddr[4];
#pragma unroll
    for (int p = 0; p < 4; p++) {
        int nr = (2 * p + (lane >> 4)) * 8 + (lane & 7);
        kAddr[p] = kBase + nr * FST * 4 + ((lane >> 3) & 1) * 16;
        vAddr[p] = vBase + nr * FST * 4 + ((lane >> 3) & 1) * 16;
    }
    const uint32_t pAddr = kBase + (wm + (lane & 15)) * FST * 4 + (lane >> 4) * 16;

    // ---- stage Q tile into K buffer 0 (raw f32), pull A-frags ----
    {
        float* Ks = (float*)dynsm;
#pragma unroll
        for (int it = 0; it < 8; it++) {
            int idx = tid + it * 128;
            int row = idx >> 4;
            int c4  = (idx & 15) << 2;
            *(float4*)&Ks[row * FST + c4] =
                *(const float4*)(Qg + base + (size_t)(i0 + row) * DD + c4);
        }
    }
    __syncthreads();
    uint32_t qf[8][4];
    {
        const float* Qs = (const float*)dynsm;
#pragma unroll
        for (int ks = 0; ks < 8; ks++) {
            qf[ks][0] = f2tf32(Qs[(wm + grp)     * FST + ks * 8 + q]);
            qf[ks][1] = f2tf32(Qs[(wm + grp + 8) * FST + ks * 8 + q]);
            qf[ks][2] = f2tf32(Qs[(wm + grp)     * FST + ks * 8 + q + 4]);
            qf[ks][3] = f2tf32(Qs[(wm + grp + 8) * FST + ks * 8 + q + 4]);
        }
    }
    __syncthreads();   // all Q reads done before cp.async overwrites buffer 0

    auto issue_tile = [&](int j, int bf) {
        const uint32_t ko = kBase + (uint32_t)bf * FBUF * 4 + stOff;
        const uint32_t vo = vBase + (uint32_t)bf * FBUF * 4 + stOff;
        const int j0 = j * 64;
#pragma unroll
        for (int it = 0; it < 8; it++) {          // FIX: full 64 rows (was 4)
            int row = srow + it * 8;
            cp16(ko + it * 8 * FST * 4,
                 Kg + base + (size_t)(j0 + row) * DD + sc4);
            cp16(vo + it * 8 * FST * 4,
                 Vtg + vtbase + (size_t)row * 1024 + j0 + sc4);
        }
        asm volatile("cp.async.commit_group;");
    };

    float oacc[8][4];
#pragma unroll
    for (int nt = 0; nt < 8; nt++)
#pragma unroll
        for (int c = 0; c < 4; c++) oacc[nt][c] = 0.f;
    float m0 = -1e30f, m1 = -1e30f, l0 = 0.f, l1 = 0.f;

    issue_tile(0, 0);

    for (int jb = 0; jb <= qb; jb++) {
        const int j0 = jb * 64;
        const int bf = jb & 1;
        const uint32_t bo = (uint32_t)bf * FBUF * 4;

        asm volatile("cp.async.wait_group 0;");
        __syncthreads();
        if (jb < qb) issue_tile(jb + 1, bf ^ 1);

        // ---- S = Q K^T (cvt post-LDSM) ----
        float sacc[8][4];
#pragma unroll
        for (int nt = 0; nt < 8; nt++)
#pragma unroll
            for (int c = 0; c < 4; c++) sacc[nt][c] = 0.f;
#pragma unroll
        for (int ks = 0; ks < 8; ks++) {
            uint32_t kb[4][4];
#pragma unroll
            for (int p = 0; p < 4; p++)
                LDSM4(kb[p][0], kb[p][1], kb[p][2], kb[p][3],
                      kAddr[p] + bo + ks * 32);
#pragma unroll
            for (int p = 0; p < 4; p++)
#pragma unroll
                for (int j = 0; j < 4; j++) kb[p][j] = u2tf32(kb[p][j]);
#pragma unroll
            for (int p = 0; p < 4; p++) {
                MMA_TF32(sacc[2 * p],     qf[ks][0], qf[ks][1], qf[ks][2], qf[ks][3],
                         kb[p][0], kb[p][1]);
                MMA_TF32(sacc[2 * p + 1], qf[ks][0], qf[ks][1], qf[ks][2], qf[ks][3],
                         kb[p][2], kb[p][3]);
            }
        }

        // ---- online softmax ----
        const bool diag = (jb == qb);
        float mx0 = -1e30f, mx1 = -1e30f;
#pragma unroll
        for (int nt = 0; nt < 8; nt++) {
            float s0 = sacc[nt][0] * 0.125f;
            float s1 = sacc[nt][1] * 0.125f;
            float s2 = sacc[nt][2] * 0.125f;
            float s3 = sacc[nt][3] * 0.125f;
            if (diag) {
                int j = j0 + nt * 8 + q * 2;
                if (j     > r0)     s0 = -1e30f;
                if (j + 1 > r0)     s1 = -1e30f;
                if (j     > r0 + 8) s2 = -1e30f;
                if (j + 1 > r0 + 8) s3 = -1e30f;
            }
            sacc[nt][0] = s0; sacc[nt][1] = s1;
            sacc[nt][2] = s2; sacc[nt][3] = s3;
            mx0 = fmaxf(mx0, fmaxf(s0, s1));
            mx1 = fmaxf(mx1, fmaxf(s2, s3));
        }
        mx0 = fmaxf(mx0, __shfl_xor_sync(0xffffffffu, mx0, 1));
        mx0 = fmaxf(mx0, __shfl_xor_sync(0xffffffffu, mx0, 2));
        mx1 = fmaxf(mx1, __shfl_xor_sync(0xffffffffu, mx1, 1));
        mx1 = fmaxf(mx1, __shfl_xor_sync(0xffffffffu, mx1, 2));
        float mn0 = fmaxf(m0, mx0), mn1 = fmaxf(m1, mx1);
        float al0 = __expf(m0 - mn0), al1 = __expf(m1 - mn1);
        m0 = mn0; m1 = mn1;
        float ps0 = 0.f, ps1 = 0.f;
#pragma unroll
        for (int nt = 0; nt < 8; nt++) {
            float p0 = __expf(sacc[nt][0] - mn0);
            float p1 = __expf(sacc[nt][1] - mn0);
            float p2 = __expf(sacc[nt][2] - mn1);
            float p3 = __expf(sacc[nt][3] - mn1);
            ps0 += p0 + p1;
            ps1 += p2 + p3;
            sacc[nt][0] = p0; sacc[nt][1] = p1;
            sacc[nt][2] = p2; sacc[nt][3] = p3;
        }
        l0 = l0 * al0 + ps0;
        l1 = l1 * al1 + ps1;
#pragma unroll
        for (int nt = 0; nt < 8; nt++) {
            oacc[nt][0] *= al0; oacc[nt][1] *= al0;
            oacc[nt][2] *= al1; oacc[nt][3] *= al1;
        }

        __syncthreads();   // all warps done reading K before P overlay

        // ---- write P (tf32) into this warp's K-buffer slice ----
        uint32_t* Psm = dynsm + bf * FBUF + wm * FST;
#pragma unroll
        for (int nt = 0; nt < 8; nt++) {
            *(uint2*)&Psm[grp * FST + nt * 8 + q * 2] =
                make_uint2(f2tf32(sacc[nt][0]), f2tf32(sacc[nt][1]));
            *(uint2*)&Psm[(grp + 8) * FST + nt * 8 + q * 2] =
                make_uint2(f2tf32(sacc[nt][2]), f2tf32(sacc[nt][3]));
        }
        __syncwarp();

        // ---- O += P V (P A-frags, Vt B-frags; cvt post-LDSM for V) ----
#pragma unroll
        for (int ks = 0; ks < 8; ks++) {
            uint32_t af[4];
            LDSM4(af[0], af[1], af[2], af[3], pAddr + bo + ks * 32);
            uint32_t vb[4][4];
#pragma unroll
            for (int p = 0; p < 4; p++)
                LDSM4(vb[p][0], vb[p][1], vb[p][2], vb[p][3],
                      vAddr[p] + bo + ks * 32);
#pragma unroll
            for (int p = 0; p < 4; p++)
#pragma unroll
                for (int j = 0; j < 4; j++) vb[p][j] = u2tf32(vb[p][j]);
#pragma unroll
            for (int p = 0; p < 4; p++) {
                MMA_TF32(oacc[2 * p],     af[0], af[1], af[2], af[3], vb[p][0], vb[p][1]);
                MMA_TF32(oacc[2 * p + 1], af[0], af[1], af[2], af[3], vb[p][2], vb[p][3]);
            }
        }
        // next iteration's wait+syncthreads fences buffer reuse
    }

    l0 += __shfl_xor_sync(0xffffffffu, l0, 1);
    l0 += __shfl_xor_sync(0xffffffffu, l0, 2);
    l1 += __shfl_xor_sync(0xffffffffu, l1, 1);
    l1 += __shfl_xor_sync(0xffffffffu, l1, 2);
    const float inv0 = 1.f / l0;
    const float inv1 = 1.f / l1;
#pragma unroll
    for (int nt = 0; nt < 8; nt++) {
        int col = nt * 8 + q * 2;
        *(float2*)(Og + base + (size_t)r0 * DD + col) =
            make_float2(oacc[nt][0] * inv0, oacc[nt][1] * inv0);
        *(float2*)(Og + base + (size_t)(r0 + 8) * DD + col) =
            make_float2(oacc[nt][2] * inv1, oacc[nt][3] * inv1);
    }
}

// ---------------------------------------------------------------------------
extern "C" void kernel_launch(void* const* d_in, const int* in_sizes, int n_in,
                              void* d_out, int out_size)
{
    (void)in_sizes; (void)n_in; (void)out_size;
    const float* x  = (const float*)d_in[0];
    const float* wq = (const float*)d_in[2];
    const float* bq = (const float*)d_in[3];
    const float* wk = (const float*)d_in[4];
    const float* bk = (const float*)d_in[5];
    const float* wv = (const float*)d_in[6];
    const float* bv = (const float*)d_in[7];
    const float* wo = (const float*)d_in[8];
    const float* bo = (const float*)d_in[9];
    float* out = (float*)d_out;

    float *We, *Qb, *Kb, *Vb, *Vt, *Ob;
    cudaGetSymbolAddress((void**)&We, g_We);
    cudaGetSymbolAddress((void**)&Qb, g_Q);
    cudaGetSymbolAddress((void**)&Kb, g_K);
    cudaGetSymbolAddress((void**)&Vb, g_V);
    cudaGetSymbolAddress((void**)&Vt, g_Vt);
    cudaGetSymbolAddress((void**)&Ob, g_O);

    cudaFuncSetAttribute(gemm_tf32,
                         cudaFuncAttributeMaxDynamicSharedMemorySize, GEMM_SMEM);
    cudaFuncSetAttribute(flash_mma,
                         cudaFuncAttributeMaxDynamicSharedMemorySize, FLASH_SMEM);

    expand_kernel<<<dim3(DD * DD / 256, 4), 256>>>(wq, wk, wv, wo);

    gemm_tf32<<<dim3(DD / 128, MM / 128, 3), 256, GEMM_SMEM>>>(
        x, We, We + DD * DD, We + 2 * DD * DD, bq, bk, bv, Qb, Kb, Vb);

    transpose_v<<<dim3(32, 32, 2), dim3(32, 8)>>>();

    flash_mma<<<dim3(32, 16), 128, FLASH_SMEM>>>(Qb, Kb, Vt, Ob);

    gemm_tf32<<<dim3(DD / 128, MM / 128, 1), 256, GEMM_SMEM>>>(
        Ob, We + 3 * DD * DD, We + 3 * DD * DD, We + 3 * DD * DD,
        bo, bo, bo, out, out, out);
}

// round 14
// speedup vs baseline: 1.0591x; 1.0591x over previous
#include <cuda_runtime.h>
#include <cstdint>

// ---------------------------------------------------------------------------
// B=2, N=1024, D=1024, K=8 (circulant), H=16, dh=64
// All GEMM operands pre-rounded to tf32 in gmem => no cvt in inner loops.
// Weights expanded TRANSPOSED: Wt[n][k] = W[k][n]  (k contiguous)
// ---------------------------------------------------------------------------
constexpr int DD = 1024;
constexpr int MM = 2048;

__device__ float g_We[4][DD * DD];   // expanded weights (tf32-rounded), Wt[n][k]
__device__ float g_X[MM * DD];       // x, tf32-rounded
__device__ float g_Q[MM * DD];
__device__ float g_K[MM * DD];
__device__ float g_V[MM * DD];
__device__ float g_Vt[MM * DD];      // V transposed per batch: [b][col][seq]
__device__ float g_O[MM * DD];       // attention out, tf32-rounded

__device__ __forceinline__ uint32_t f2tf32(float f) {
    uint32_t r;
    asm("cvt.rna.tf32.f32 %0, %1;" : "=r"(r) : "f"(f));
    return r;
}

#define MMA_TF32(ACC, A0, A1, A2, A3, B0, B1)                            \
    asm volatile(                                                        \
        "mma.sync.aligned.m16n8k8.row.col.f32.tf32.tf32.f32 "            \
        "{%0,%1,%2,%3}, {%4,%5,%6,%7}, {%8,%9}, {%0,%1,%2,%3};"          \
        : "+f"((ACC)[0]), "+f"((ACC)[1]), "+f"((ACC)[2]), "+f"((ACC)[3]) \
        : "r"(A0), "r"(A1), "r"(A2), "r"(A3), "r"(B0), "r"(B1))

#define LDSM4(R0, R1, R2, R3, ADDR)                                      \
    asm volatile("ldmatrix.sync.aligned.m8n8.x4.shared.b16 "             \
                 "{%0,%1,%2,%3}, [%4];"                                  \
                 : "=r"(R0), "=r"(R1), "=r"(R2), "=r"(R3) : "r"(ADDR))

__device__ __forceinline__ void cp16(uint32_t smem, const void* g) {
    asm volatile("cp.async.ca.shared.global [%0], [%1], 16;\n"
                 :: "r"(smem), "l"(g));
}

extern __shared__ uint32_t dynsm[];

// ---------------------------------------------------------------------------
// Expand circulant blocks TRANSPOSED + tf32-round:
//   dst[n][k] = tf32(w[n/8][k/8][(n-k)&7])
// ---------------------------------------------------------------------------
__global__ void expand_kernel(const float* __restrict__ w0,
                              const float* __restrict__ w1,
                              const float* __restrict__ w2,
                              const float* __restrict__ w3)
{
    const float* w;
    switch (blockIdx.y) {
        case 0:  w = w0; break;
        case 1:  w = w1; break;
        case 2:  w = w2; break;
        default: w = w3; break;
    }
    float* dst = g_We[blockIdx.y];
    int idx = blockIdx.x * 256 + threadIdx.x;
    int n = idx >> 10;
    int k = idx & 1023;
    dst[idx] = __uint_as_float(
        f2tf32(w[((n >> 3) << 10) + ((k >> 3) << 3) + ((n - k) & 7)]));
}

// x -> tf32-rounded copy
__global__ void convert_x(const float* __restrict__ x)
{
    int idx = (blockIdx.x * 256 + threadIdx.x) * 4;
    float4 v = *(const float4*)(x + idx);
    float4 r;
    r.x = __uint_as_float(f2tf32(v.x));
    r.y = __uint_as_float(f2tf32(v.y));
    r.z = __uint_as_float(f2tf32(v.z));
    r.w = __uint_as_float(f2tf32(v.w));
    *(float4*)(g_X + idx) = r;
}

// ---------------------------------------------------------------------------
// Per-batch transpose: g_Vt[b][c][s] = g_V[b][s][c].  Tiled 32x32.
// ---------------------------------------------------------------------------
__global__ __launch_bounds__(256)
void transpose_v()
{
    __shared__ float t[32][33];
    const int b  = blockIdx.z;
    const int s0 = blockIdx.x * 32;
    const int c0 = blockIdx.y * 32;
    const float* src = g_V + (size_t)b * (1024 * 1024);
    float* dst = g_Vt + (size_t)b * (1024 * 1024);
#pragma unroll
    for (int i = 0; i < 4; i++) {
        int row = threadIdx.y + i * 8;
        t[row][threadIdx.x] = src[(size_t)(s0 + row) * 1024 + c0 + threadIdx.x];
    }
    __syncthreads();
#pragma unroll
    for (int i = 0; i < 4; i++) {
        int row = threadIdx.y + i * 8;
        dst[(size_t)(c0 + row) * 1024 + s0 + threadIdx.x] = t[threadIdx.x][row];
    }
}

// ---------------------------------------------------------------------------
// TF32 GEMM + bias: 128x128 tile, BK=16, 8 warps of 32x64, ldmatrix frags,
// 4-stage cp.async pipeline. Operands pre-rounded tf32 => NO cvt inner loop.
// ---------------------------------------------------------------------------
constexpr int GST  = 20;           // smem row stride (floats)
constexpr int BUFW = 128 * GST;    // words per (A or B) stage
constexpr int NST  = 4;            // pipeline stages
constexpr int GEMM_SMEM = 2 * NST * BUFW * 4;   // 81920 bytes

__global__ __launch_bounds__(256, 2)
void gemm_tf32(const float* __restrict__ A,
               const float* __restrict__ B0, const float* __restrict__ B1,
               const float* __restrict__ B2,
               const float* __restrict__ bi0, const float* __restrict__ bi1,
               const float* __restrict__ bi2,
               float* __restrict__ C0, float* __restrict__ C1,
               float* __restrict__ C2)
{
    const float* Bm; const float* bias; float* C;
    if (blockIdx.z == 0)      { Bm = B0; bias = bi0; C = C0; }
    else if (blockIdx.z == 1) { Bm = B1; bias = bi1; C = C1; }
    else                      { Bm = B2; bias = bi2; C = C2; }

    const int tid  = threadIdx.x;
    const int warp = tid >> 5;
    const int lane = tid & 31;
    const int grp  = lane >> 2;
    const int q    = lane & 3;

    const int cRow = blockIdx.y * 128;
    const int cCol = blockIdx.x * 128;
    const int wm   = (warp & 3) * 32;
    const int wn   = (warp >> 2) * 64;

    const int sr = tid >> 2;
    const int sc = (tid & 3) * 4;

    const float* Ap = A  + (size_t)(cRow + sr) * DD + sc;
    const float* Bp = Bm + (size_t)(cCol + sr) * DD + sc;

    const uint32_t aBase = (uint32_t)__cvta_generic_to_shared(dynsm);
    const uint32_t bBase = aBase + NST * BUFW * 4;

    const uint32_t sA0 = aBase + (sr * GST + sc) * 4;
    const uint32_t sA1 = sA0 + 64 * GST * 4;
    const uint32_t sB0 = bBase + (sr * GST + sc) * 4;
    const uint32_t sB1 = sB0 + 64 * GST * 4;

    uint32_t aAddr[2];
#pragma unroll
    for (int mi = 0; mi < 2; mi++)
        aAddr[mi] = aBase + ((wm + mi * 16 + (lane & 15)) * GST) * 4 +
                    (lane >> 4) * 16;
    uint32_t bAddr[4];
#pragma unroll
    for (int p = 0; p < 4; p++)
        bAddr[p] = bBase + ((wn + (2 * p + (lane >> 4)) * 8 + (lane & 7)) * GST) * 4 +
                   ((lane >> 3) & 1) * 16;

    float acc[2][8][4];
#pragma unroll
    for (int mi = 0; mi < 2; mi++)
#pragma unroll
        for (int ni = 0; ni < 8; ni++)
#pragma unroll
            for (int c = 0; c < 4; c++) acc[mi][ni][c] = 0.f;

    auto issue_stage = [&](int s, int kb) {
        const uint32_t so = (uint32_t)s * (BUFW * 4);
        cp16(sA0 + so, Ap + kb);
        cp16(sA1 + so, Ap + 64 * DD + kb);
        cp16(sB0 + so, Bp + kb);
        cp16(sB1 + so, Bp + 64 * DD + kb);
        asm volatile("cp.async.commit_group;");
    };

    auto compute = [&](int it) {
        const uint32_t so = (uint32_t)(it & 3) * (BUFW * 4);
#pragma unroll
        for (int kc = 0; kc < 2; kc++) {
            const uint32_t ko = so + kc * 32;
            uint32_t a0[4], a1[4];
            LDSM4(a0[0], a0[1], a0[2], a0[3], aAddr[0] + ko);
            LDSM4(a1[0], a1[1], a1[2], a1[3], aAddr[1] + ko);
            uint32_t bv[4][4];
#pragma unroll
            for (int p = 0; p < 4; p++)
                LDSM4(bv[p][0], bv[p][1], bv[p][2], bv[p][3], bAddr[p] + ko);
#pragma unroll
            for (int p = 0; p < 4; p++) {
                MMA_TF32(acc[0][2 * p],     a0[0], a0[1], a0[2], a0[3], bv[p][0], bv[p][1]);
                MMA_TF32(acc[0][2 * p + 1], a0[0], a0[1], a0[2], a0[3], bv[p][2], bv[p][3]);
                MMA_TF32(acc[1][2 * p],     a1[0], a1[1], a1[2], a1[3], bv[p][0], bv[p][1]);
                MMA_TF32(acc[1][2 * p + 1], a1[0], a1[1], a1[2], a1[3], bv[p][2], bv[p][3]);
            }
        }
    };

    issue_stage(0, 0);
    issue_stage(1, 16);
    issue_stage(2, 32);

    for (int it = 0; it <= 60; it++) {
        asm volatile("cp.async.wait_group 2;");
        __syncthreads();
        compute(it);
        __syncthreads();
        issue_stage((it + 3) & 3, (it + 3) * 16);
    }
    asm volatile("cp.async.wait_group 2;");
    __syncthreads();
    compute(61);
    asm volatile("cp.async.wait_group 1;");
    __syncthreads();
    compute(62);
    asm volatile("cp.async.wait_group 0;");
    __syncthreads();
    compute(63);

#pragma unroll
    for (int mi = 0; mi < 2; mi++) {
#pragma unroll
        for (int ni = 0; ni < 8; ni++) {
            int row = cRow + wm + mi * 16 + grp;
            int col = cCol + wn + ni * 8 + q * 2;
            float bx = bias[col], by = bias[col + 1];
            *(float2*)(C + (size_t)row * DD + col) =
                make_float2(acc[mi][ni][0] + bx, acc[mi][ni][1] + by);
            *(float2*)(C + (size_t)(row + 8) * DD + col) =
                make_float2(acc[mi][ni][2] + bx, acc[mi][ni][3] + by);
        }
    }
}

// ---------------------------------------------------------------------------
// Tensor-core causal flash attention (R10 sync-staging version).
// Ksm: K natural [seq][dh] stride 68 (doubles as P region).
// Vsm: Vt tile [dh][seq] stride 68 (stages Q first). cvt at store.
// Epilogue writes O tf32-rounded (out-proj input).
// 0.125 scale folded into Q fragments (exact, power of two).
// ---------------------------------------------------------------------------
constexpr int KST = 68;
constexpr int VST = 68;

__global__ __launch_bounds__(128, 3)
void flash_mma(const float* __restrict__ Qg, const float* __restrict__ Kg,
               const float* __restrict__ Vtg, float* __restrict__ Og)
{
    __shared__ uint32_t Ksm[64 * KST];
    __shared__ uint32_t Vsm[64 * VST];

    const int tid  = threadIdx.x;
    const int warp = tid >> 5;
    const int lane = tid & 31;
    const int grp  = lane >> 2;
    const int q    = lane & 3;

    const int qb = 15 - blockIdx.y;
    const int i0 = qb * 64;
    const int h  = blockIdx.x & 15;
    const int b  = blockIdx.x >> 4;
    const size_t base   = (size_t)b * (1024 * 1024) + h * 64;
    const size_t vtbase = (size_t)b * (1024 * 1024) + (size_t)(h * 64) * 1024;

    const int wm = warp * 16;
    const int r0 = i0 + wm + grp;

    const uint32_t kBase = (uint32_t)__cvta_generic_to_shared(Ksm);
    const uint32_t vBase = (uint32_t)__cvta_generic_to_shared(Vsm);
    uint32_t kAddr[4], vAddr[4];
#pragma unroll
    for (int p = 0; p < 4; p++) {
        int nr = (2 * p + (lane >> 4)) * 8 + (lane & 7);
        kAddr[p] = kBase + nr * KST * 4 + ((lane >> 3) & 1) * 16;
        vAddr[p] = vBase + nr * VST * 4 + ((lane >> 3) & 1) * 16;
    }
    const uint32_t pAddr = kBase + (wm + (lane & 15)) * KST * 4 + (lane >> 4) * 16;

    // ---- stage Q tile into Vsm (natural [qrow][dh]), pull A-frags ----
#pragma unroll
    for (int it = 0; it < 8; it++) {
        int idx = tid + it * 128;
        int row = idx >> 4;
        int c4  = (idx & 15) << 2;
        *(float4*)&((float*)Vsm)[row * VST + c4] =
            *(const float4*)(Qg + base + (size_t)(i0 + row) * DD + c4);
    }
    __syncthreads();
    uint32_t qf[8][4];
    {
        const float* Qs = (const float*)Vsm;
#pragma unroll
        for (int ks = 0; ks < 8; ks++) {
            qf[ks][0] = f2tf32(Qs[(wm + grp)     * VST + ks * 8 + q] * 0.125f);
            qf[ks][1] = f2tf32(Qs[(wm + grp + 8) * VST + ks * 8 + q] * 0.125f);
            qf[ks][2] = f2tf32(Qs[(wm + grp)     * VST + ks * 8 + q + 4] * 0.125f);
            qf[ks][3] = f2tf32(Qs[(wm + grp + 8) * VST + ks * 8 + q + 4] * 0.125f);
        }
    }
    __syncthreads();

    float oacc[8][4];
#pragma unroll
    for (int nt = 0; nt < 8; nt++)
#pragma unroll
        for (int c = 0; c < 4; c++) oacc[nt][c] = 0.f;
    float m0 = -1e30f, m1 = -1e30f, l0 = 0.f, l1 = 0.f;

    for (int jb = 0; jb <= qb; jb++) {
        const int j0 = jb * 64;

#pragma unroll
        for (int it = 0; it < 8; it++) {
            int idx = tid + it * 128;
            int row = idx >> 4;
            int c4  = (idx & 15) << 2;
            float4 k4 = *(const float4*)(Kg + base + (size_t)(j0 + row) * DD + c4);
            float4 v4 = *(const float4*)(Vtg + vtbase + (size_t)row * 1024 + j0 + c4);
            *(uint4*)&Ksm[row * KST + c4] =
                make_uint4(f2tf32(k4.x), f2tf32(k4.y), f2tf32(k4.z), f2tf32(k4.w));
            *(uint4*)&Vsm[row * VST + c4] =
                make_uint4(f2tf32(v4.x), f2tf32(v4.y), f2tf32(v4.z), f2tf32(v4.w));
        }
        __syncthreads();

        // ---- S = (Q/8) K^T ----
        float sacc[8][4];
#pragma unroll
        for (int nt = 0; nt < 8; nt++)
#pragma unroll
            for (int c = 0; c < 4; c++) sacc[nt][c] = 0.f;
#pragma unroll
        for (int ks = 0; ks < 8; ks++) {
            uint32_t kb[4][4];
#pragma unroll
            for (int p = 0; p < 4; p++)
                LDSM4(kb[p][0], kb[p][1], kb[p][2], kb[p][3], kAddr[p] + ks * 32);
#pragma unroll
            for (int p = 0; p < 4; p++) {
                MMA_TF32(sacc[2 * p],     qf[ks][0], qf[ks][1], qf[ks][2], qf[ks][3],
                         kb[p][0], kb[p][1]);
                MMA_TF32(sacc[2 * p + 1], qf[ks][0], qf[ks][1], qf[ks][2], qf[ks][3],
                         kb[p][2], kb[p][3]);
            }
        }

        // ---- online softmax (scores already scaled) ----
        const bool diag = (jb == qb);
        float mx0 = -1e30f, mx1 = -1e30f;
#pragma unroll
        for (int nt = 0; nt < 8; nt++) {
            float s0 = sacc[nt][0];
            float s1 = sacc[nt][1];
            float s2 = sacc[nt][2];
            float s3 = sacc[nt][3];
            if (diag) {
                int j = j0 + nt * 8 + q * 2;
                if (j     > r0)     s0 = -1e30f;
                if (j + 1 > r0)     s1 = -1e30f;
                if (j     > r0 + 8) s2 = -1e30f;
                if (j + 1 > r0 + 8) s3 = -1e30f;
            }
            sacc[nt][0] = s0; sacc[nt][1] = s1;
            sacc[nt][2] = s2; sacc[nt][3] = s3;
            mx0 = fmaxf(mx0, fmaxf(s0, s1));
            mx1 = fmaxf(mx1, fmaxf(s2, s3));
        }
        mx0 = fmaxf(mx0, __shfl_xor_sync(0xffffffffu, mx0, 1));
        mx0 = fmaxf(mx0, __shfl_xor_sync(0xffffffffu, mx0, 2));
        mx1 = fmaxf(mx1, __shfl_xor_sync(0xffffffffu, mx1, 1));
        mx1 = fmaxf(mx1, __shfl_xor_sync(0xffffffffu, mx1, 2));
        float mn0 = fmaxf(m0, mx0), mn1 = fmaxf(m1, mx1);
        float al0 = __expf(m0 - mn0), al1 = __expf(m1 - mn1);
        m0 = mn0; m1 = mn1;
        float ps0 = 0.f, ps1 = 0.f;
#pragma unroll
        for (int nt = 0; nt < 8; nt++) {
            float p0 = __expf(sacc[nt][0] - mn0);
            float p1 = __expf(sacc[nt][1] - mn0);
            float p2 = __expf(sacc[nt][2] - mn1);
            float p3 = __expf(sacc[nt][3] - mn1);
            ps0 += p0 + p1;
            ps1 += p2 + p3;
            sacc[nt][0] = p0; sacc[nt][1] = p1;
            sacc[nt][2] = p2; sacc[nt][3] = p3;
        }
        l0 = l0 * al0 + ps0;
        l1 = l1 * al1 + ps1;
#pragma unroll
        for (int nt = 0; nt < 8; nt++) {
            oacc[nt][0] *= al0; oacc[nt][1] *= al0;
            oacc[nt][2] *= al1; oacc[nt][3] *= al1;
        }

        __syncthreads();   // all warps done reading K before P overlay

        // ---- write P (tf32) into this warp's Ksm slice ----
        uint32_t* Psm = Ksm + wm * KST;
#pragma unroll
        for (int nt = 0; nt < 8; nt++) {
            *(uint2*)&Psm[grp * KST + nt * 8 + q * 2] =
                make_uint2(f2tf32(sacc[nt][0]), f2tf32(sacc[nt][1]));
            *(uint2*)&Psm[(grp + 8) * KST + nt * 8 + q * 2] =
                make_uint2(f2tf32(sacc[nt][2]), f2tf32(sacc[nt][3]));
        }
        __syncwarp();

        // ---- O += P V (LDSM frags) ----
#pragma unroll
        for (int ks = 0; ks < 8; ks++) {
            uint32_t af[4];
            LDSM4(af[0], af[1], af[2], af[3], pAddr + ks * 32);
            uint32_t vb[4][4];
#pragma unroll
            for (int p = 0; p < 4; p++)
                LDSM4(vb[p][0], vb[p][1], vb[p][2], vb[p][3], vAddr[p] + ks * 32);
#pragma unroll
            for (int p = 0; p < 4; p++) {
                MMA_TF32(oacc[2 * p],     af[0], af[1], af[2], af[3], vb[p][0], vb[p][1]);
                MMA_TF32(oacc[2 * p + 1], af[0], af[1], af[2], af[3], vb[p][2], vb[p][3]);
            }
        }
        __syncthreads();
    }

    l0 += __shfl_xor_sync(0xffffffffu, l0, 1);
    l0 += __shfl_xor_sync(0xffffffffu, l0, 2);
    l1 += __shfl_xor_sync(0xffffffffu, l1, 1);
    l1 += __shfl_xor_sync(0xffffffffu, l1, 2);
    const float inv0 = 1.f / l0;
    const float inv1 = 1.f / l1;

    // epilogue: tf32-rounded O (input to the out-projection GEMM)
#pragma unroll
    for (int nt = 0; nt < 8; nt++) {
        int col = nt * 8 + q * 2;
        uint2 w0 = make_uint2(f2tf32(oacc[nt][0] * inv0), f2tf32(oacc[nt][1] * inv0));
        uint2 w1 = make_uint2(f2tf32(oacc[nt][2] * inv1), f2tf32(oacc[nt][3] * inv1));
        *(uint2*)(Og + base + (size_t)r0 * DD + col) = w0;
        *(uint2*)(Og + base + (size_t)(r0 + 8) * DD + col) = w1;
    }
}

// ---------------------------------------------------------------------------
extern "C" void kernel_launch(void* const* d_in, const int* in_sizes, int n_in,
                              void* d_out, int out_size)
{
    (void)in_sizes; (void)n_in; (void)out_size;
    const float* x  = (const float*)d_in[0];
    const float* wq = (const float*)d_in[2];
    const float* bq = (const float*)d_in[3];
    const float* wk = (const float*)d_in[4];
    const float* bk = (const float*)d_in[5];
    const float* wv = (const float*)d_in[6];
    const float* bv = (const float*)d_in[7];
    const float* wo = (const float*)d_in[8];
    const float* bo = (const float*)d_in[9];
    float* out = (float*)d_out;

    float *We, *X, *Qb, *Kb, *Vb, *Vt, *Ob;
    cudaGetSymbolAddress((void**)&We, g_We);
    cudaGetSymbolAddress((void**)&X,  g_X);
    cudaGetSymbolAddress((void**)&Qb, g_Q);
    cudaGetSymbolAddress((void**)&Kb, g_K);
    cudaGetSymbolAddress((void**)&Vb, g_V);
    cudaGetSymbolAddress((void**)&Vt, g_Vt);
    cudaGetSymbolAddress((void**)&Ob, g_O);

    cudaFuncSetAttribute(gemm_tf32,
                         cudaFuncAttributeMaxDynamicSharedMemorySize, GEMM_SMEM);

    expand_kernel<<<dim3(DD * DD / 256, 4), 256>>>(wq, wk, wv, wo);
    convert_x<<<MM * DD / 1024, 256>>>(x);

    gemm_tf32<<<dim3(DD / 128, MM / 128, 3), 256, GEMM_SMEM>>>(
        X, We, We + DD * DD, We + 2 * DD * DD, bq, bk, bv, Qb, Kb, Vb);

    transpose_v<<<dim3(32, 32, 2), dim3(32, 8)>>>();

    flash_mma<<<dim3(32, 16), 128>>>(Qb, Kb, Vt, Ob);

    gemm_tf32<<<dim3(DD / 128, MM / 128, 1), 256, GEMM_SMEM>>>(
        Ob, We + 3 * DD * DD, We + 3 * DD * DD, We + 3 * DD * DD,
        bo, bo, bo, out, out, out);
}

// round 15
// speedup vs baseline: 1.0802x; 1.0198x over previous
#include <cuda_runtime.h>
#include <cstdint>

// ---------------------------------------------------------------------------
// B=2, N=1024, D=1024, K=8 (circulant), H=16, dh=64
// All GEMM/flash operands pre-rounded to tf32 in gmem => no cvt in hot loops.
// Weights expanded TRANSPOSED: Wt[n][k] = W[k][n]  (k contiguous)
// ---------------------------------------------------------------------------
constexpr int DD = 1024;
constexpr int MM = 2048;

__device__ float g_We[4][DD * DD];   // expanded weights (tf32-rounded), Wt[n][k]
__device__ float g_X[MM * DD];       // x, tf32-rounded
__device__ float g_Q[MM * DD];       // tf32-rounded (QKV gemm epilogue)
__device__ float g_K[MM * DD];       // tf32-rounded
__device__ float g_V[MM * DD];       // tf32-rounded
__device__ float g_Vt[MM * DD];      // V transposed per batch: [b][col][seq]
__device__ float g_O[MM * DD];       // attention out, tf32-rounded

__device__ __forceinline__ uint32_t f2tf32(float f) {
    uint32_t r;
    asm("cvt.rna.tf32.f32 %0, %1;" : "=r"(r) : "f"(f));
    return r;
}

#define MMA_TF32(ACC, A0, A1, A2, A3, B0, B1)                            \
    asm volatile(                                                        \
        "mma.sync.aligned.m16n8k8.row.col.f32.tf32.tf32.f32 "            \
        "{%0,%1,%2,%3}, {%4,%5,%6,%7}, {%8,%9}, {%0,%1,%2,%3};"          \
        : "+f"((ACC)[0]), "+f"((ACC)[1]), "+f"((ACC)[2]), "+f"((ACC)[3]) \
        : "r"(A0), "r"(A1), "r"(A2), "r"(A3), "r"(B0), "r"(B1))

#define LDSM4(R0, R1, R2, R3, ADDR)                                      \
    asm volatile("ldmatrix.sync.aligned.m8n8.x4.shared.b16 "             \
                 "{%0,%1,%2,%3}, [%4];"                                  \
                 : "=r"(R0), "=r"(R1), "=r"(R2), "=r"(R3) : "r"(ADDR))

__device__ __forceinline__ void cp16(uint32_t smem, const void* g) {
    asm volatile("cp.async.ca.shared.global [%0], [%1], 16;\n"
                 :: "r"(smem), "l"(g));
}

extern __shared__ uint32_t dynsm[];

// ---------------------------------------------------------------------------
// Expand circulant blocks TRANSPOSED + tf32-round
// ---------------------------------------------------------------------------
__global__ void expand_kernel(const float* __restrict__ w0,
                              const float* __restrict__ w1,
                              const float* __restrict__ w2,
                              const float* __restrict__ w3)
{
    const float* w;
    switch (blockIdx.y) {
        case 0:  w = w0; break;
        case 1:  w = w1; break;
        case 2:  w = w2; break;
        default: w = w3; break;
    }
    float* dst = g_We[blockIdx.y];
    int idx = blockIdx.x * 256 + threadIdx.x;
    int n = idx >> 10;
    int k = idx & 1023;
    dst[idx] = __uint_as_float(
        f2tf32(w[((n >> 3) << 10) + ((k >> 3) << 3) + ((n - k) & 7)]));
}

__global__ void convert_x(const float* __restrict__ x)
{
    int idx = (blockIdx.x * 256 + threadIdx.x) * 4;
    float4 v = *(const float4*)(x + idx);
    float4 r;
    r.x = __uint_as_float(f2tf32(v.x));
    r.y = __uint_as_float(f2tf32(v.y));
    r.z = __uint_as_float(f2tf32(v.z));
    r.w = __uint_as_float(f2tf32(v.w));
    *(float4*)(g_X + idx) = r;
}

// ---------------------------------------------------------------------------
// Per-batch transpose: g_Vt[b][c][s] = g_V[b][s][c].  Tiled 32x32.
// ---------------------------------------------------------------------------
__global__ __launch_bounds__(256)
void transpose_v()
{
    __shared__ float t[32][33];
    const int b  = blockIdx.z;
    const int s0 = blockIdx.x * 32;
    const int c0 = blockIdx.y * 32;
    const float* src = g_V + (size_t)b * (1024 * 1024);
    float* dst = g_Vt + (size_t)b * (1024 * 1024);
#pragma unroll
    for (int i = 0; i < 4; i++) {
        int row = threadIdx.y + i * 8;
        t[row][threadIdx.x] = src[(size_t)(s0 + row) * 1024 + c0 + threadIdx.x];
    }
    __syncthreads();
#pragma unroll
    for (int i = 0; i < 4; i++) {
        int row = threadIdx.y + i * 8;
        dst[(size_t)(c0 + row) * 1024 + s0 + threadIdx.x] = t[threadIdx.x][row];
    }
}

// ---------------------------------------------------------------------------
// TF32 GEMM + bias: 128x128 tile, BK=16, 8 warps of 32x64, ldmatrix frags,
// 4-stage cp.async pipeline, ONE barrier per iteration (prefetch-early).
// ROUND: tf32-round the outputs (QKV) or keep fp32 (final projection).
// ---------------------------------------------------------------------------
constexpr int GST  = 20;
constexpr int BUFW = 128 * GST;
constexpr int NST  = 4;
constexpr int GEMM_SMEM = 2 * NST * BUFW * 4;   // 81920 bytes

template <bool ROUND>
__global__ __launch_bounds__(256, 2)
void gemm_tf32(const float* __restrict__ A,
               const float* __restrict__ B0, const float* __restrict__ B1,
               const float* __restrict__ B2,
               const float* __restrict__ bi0, const float* __restrict__ bi1,
               const float* __restrict__ bi2,
               float* __restrict__ C0, float* __restrict__ C1,
               float* __restrict__ C2)
{
    const float* Bm; const float* bias; float* C;
    if (blockIdx.z == 0)      { Bm = B0; bias = bi0; C = C0; }
    else if (blockIdx.z == 1) { Bm = B1; bias = bi1; C = C1; }
    else                      { Bm = B2; bias = bi2; C = C2; }

    const int tid  = threadIdx.x;
    const int warp = tid >> 5;
    const int lane = tid & 31;
    const int grp  = lane >> 2;
    const int q    = lane & 3;

    const int cRow = blockIdx.y * 128;
    const int cCol = blockIdx.x * 128;
    const int wm   = (warp & 3) * 32;
    const int wn   = (warp >> 2) * 64;

    const int sr = tid >> 2;
    const int sc = (tid & 3) * 4;

    const float* Ap = A  + (size_t)(cRow + sr) * DD + sc;
    const float* Bp = Bm + (size_t)(cCol + sr) * DD + sc;

    const uint32_t aBase = (uint32_t)__cvta_generic_to_shared(dynsm);
    const uint32_t bBase = aBase + NST * BUFW * 4;

    const uint32_t sA0 = aBase + (sr * GST + sc) * 4;
    const uint32_t sA1 = sA0 + 64 * GST * 4;
    const uint32_t sB0 = bBase + (sr * GST + sc) * 4;
    const uint32_t sB1 = sB0 + 64 * GST * 4;

    uint32_t aAddr[2];
#pragma unroll
    for (int mi = 0; mi < 2; mi++)
        aAddr[mi] = aBase + ((wm + mi * 16 + (lane & 15)) * GST) * 4 +
                    (lane >> 4) * 16;
    uint32_t bAddr[4];
#pragma unroll
    for (int p = 0; p < 4; p++)
        bAddr[p] = bBase + ((wn + (2 * p + (lane >> 4)) * 8 + (lane & 7)) * GST) * 4 +
                   ((lane >> 3) & 1) * 16;

    float acc[2][8][4];
#pragma unroll
    for (int mi = 0; mi < 2; mi++)
#pragma unroll
        for (int ni = 0; ni < 8; ni++)
#pragma unroll
            for (int c = 0; c < 4; c++) acc[mi][ni][c] = 0.f;

    auto issue_stage = [&](int s, int kb) {
        const uint32_t so = (uint32_t)s * (BUFW * 4);
        cp16(sA0 + so, Ap + kb);
        cp16(sA1 + so, Ap + 64 * DD + kb);
        cp16(sB0 + so, Bp + kb);
        cp16(sB1 + so, Bp + 64 * DD + kb);
        asm volatile("cp.async.commit_group;");
    };

    auto compute = [&](int it) {
        const uint32_t so = (uint32_t)(it & 3) * (BUFW * 4);
#pragma unroll
        for (int kc = 0; kc < 2; kc++) {
            const uint32_t ko = so + kc * 32;
            uint32_t a0[4], a1[4];
            LDSM4(a0[0], a0[1], a0[2], a0[3], aAddr[0] + ko);
            LDSM4(a1[0], a1[1], a1[2], a1[3], aAddr[1] + ko);
            uint32_t bv[4][4];
#pragma unroll
            for (int p = 0; p < 4; p++)
                LDSM4(bv[p][0], bv[p][1], bv[p][2], bv[p][3], bAddr[p] + ko);
#pragma unroll
            for (int p = 0; p < 4; p++) {
                MMA_TF32(acc[0][2 * p],     a0[0], a0[1], a0[2], a0[3], bv[p][0], bv[p][1]);
                MMA_TF32(acc[0][2 * p + 1], a0[0], a0[1], a0[2], a0[3], bv[p][2], bv[p][3]);
                MMA_TF32(acc[1][2 * p],     a1[0], a1[1], a1[2], a1[3], bv[p][0], bv[p][1]);
                MMA_TF32(acc[1][2 * p + 1], a1[0], a1[1], a1[2], a1[3], bv[p][2], bv[p][3]);
            }
        }
    };

    issue_stage(0, 0);
    issue_stage(1, 16);
    issue_stage(2, 32);

    // One barrier per iter: the top sync already fences compute(it-1) readers
    // of the buffer issue_stage is about to overwrite.
    for (int it = 0; it <= 60; it++) {
        asm volatile("cp.async.wait_group 2;");
        __syncthreads();
        issue_stage((it + 3) & 3, (it + 3) * 16);
        compute(it);
    }
    asm volatile("cp.async.wait_group 2;");
    __syncthreads();
    compute(61);
    asm volatile("cp.async.wait_group 1;");
    __syncthreads();
    compute(62);
    asm volatile("cp.async.wait_group 0;");
    __syncthreads();
    compute(63);

#pragma unroll
    for (int mi = 0; mi < 2; mi++) {
#pragma unroll
        for (int ni = 0; ni < 8; ni++) {
            int row = cRow + wm + mi * 16 + grp;
            int col = cCol + wn + ni * 8 + q * 2;
            float bx = bias[col], by = bias[col + 1];
            float v0 = acc[mi][ni][0] + bx, v1 = acc[mi][ni][1] + by;
            float v2 = acc[mi][ni][2] + bx, v3 = acc[mi][ni][3] + by;
            if (ROUND) {
                v0 = __uint_as_float(f2tf32(v0));
                v1 = __uint_as_float(f2tf32(v1));
                v2 = __uint_as_float(f2tf32(v2));
                v3 = __uint_as_float(f2tf32(v3));
            }
            *(float2*)(C + (size_t)row * DD + col)       = make_float2(v0, v1);
            *(float2*)(C + (size_t)(row + 8) * DD + col) = make_float2(v2, v3);
        }
    }
}

// ---------------------------------------------------------------------------
// Tensor-core causal flash attention. Inputs pre-rounded tf32 => staging is
// a pure copy (no cvt). Ksm doubles as P region; Vsm holds Vt tile.
// 0.125 folded into Q frags (exact). Epilogue writes tf32-rounded O.
// ---------------------------------------------------------------------------
constexpr int KST = 68;
constexpr int VST = 68;

__global__ __launch_bounds__(128, 3)
void flash_mma(const float* __restrict__ Qg, const float* __restrict__ Kg,
               const float* __restrict__ Vtg, float* __restrict__ Og)
{
    __shared__ uint32_t Ksm[64 * KST];
    __shared__ uint32_t Vsm[64 * VST];

    const int tid  = threadIdx.x;
    const int warp = tid >> 5;
    const int lane = tid & 31;
    const int grp  = lane >> 2;
    const int q    = lane & 3;

    const int qb = 15 - blockIdx.y;
    const int i0 = qb * 64;
    const int h  = blockIdx.x & 15;
    const int b  = blockIdx.x >> 4;
    const size_t base   = (size_t)b * (1024 * 1024) + h * 64;
    const size_t vtbase = (size_t)b * (1024 * 1024) + (size_t)(h * 64) * 1024;

    const int wm = warp * 16;
    const int r0 = i0 + wm + grp;

    const uint32_t kBase = (uint32_t)__cvta_generic_to_shared(Ksm);
    const uint32_t vBase = (uint32_t)__cvta_generic_to_shared(Vsm);
    uint32_t kAddr[4], vAddr[4];
#pragma unroll
    for (int p = 0; p < 4; p++) {
        int nr = (2 * p + (lane >> 4)) * 8 + (lane & 7);
        kAddr[p] = kBase + nr * KST * 4 + ((lane >> 3) & 1) * 16;
        vAddr[p] = vBase + nr * VST * 4 + ((lane >> 3) & 1) * 16;
    }
    const uint32_t pAddr = kBase + (wm + (lane & 15)) * KST * 4 + (lane >> 4) * 16;

    // ---- stage Q tile into Vsm (pure copy), pull A-frags ----
#pragma unroll
    for (int it = 0; it < 8; it++) {
        int idx = tid + it * 128;
        int row = idx >> 4;
        int c4  = (idx & 15) << 2;
        *(float4*)&((float*)Vsm)[row * VST + c4] =
            *(const float4*)(Qg + base + (size_t)(i0 + row) * DD + c4);
    }
    __syncthreads();
    uint32_t qf[8][4];
    {
        const float* Qs = (const float*)Vsm;
#pragma unroll
        for (int ks = 0; ks < 8; ks++) {
            qf[ks][0] = f2tf32(Qs[(wm + grp)     * VST + ks * 8 + q] * 0.125f);
            qf[ks][1] = f2tf32(Qs[(wm + grp + 8) * VST + ks * 8 + q] * 0.125f);
            qf[ks][2] = f2tf32(Qs[(wm + grp)     * VST + ks * 8 + q + 4] * 0.125f);
            qf[ks][3] = f2tf32(Qs[(wm + grp + 8) * VST + ks * 8 + q + 4] * 0.125f);
        }
    }
    __syncthreads();

    float oacc[8][4];
#pragma unroll
    for (int nt = 0; nt < 8; nt++)
#pragma unroll
        for (int c = 0; c < 4; c++) oacc[nt][c] = 0.f;
    float m0 = -1e30f, m1 = -1e30f, l0 = 0.f, l1 = 0.f;

    for (int jb = 0; jb <= qb; jb++) {
        const int j0 = jb * 64;

        // ---- stage K natural, Vt natural: pure uint4 copies ----
#pragma unroll
        for (int it = 0; it < 8; it++) {
            int idx = tid + it * 128;
            int row = idx >> 4;
            int c4  = (idx & 15) << 2;
            *(uint4*)&Ksm[row * KST + c4] =
                *(const uint4*)(Kg + base + (size_t)(j0 + row) * DD + c4);
            *(uint4*)&Vsm[row * VST + c4] =
                *(const uint4*)(Vtg + vtbase + (size_t)row * 1024 + j0 + c4);
        }
        __syncthreads();

        // ---- S = (Q/8) K^T ----
        float sacc[8][4];
#pragma unroll
        for (int nt = 0; nt < 8; nt++)
#pragma unroll
            for (int c = 0; c < 4; c++) sacc[nt][c] = 0.f;
#pragma unroll
        for (int ks = 0; ks < 8; ks++) {
            uint32_t kb[4][4];
#pragma unroll
            for (int p = 0; p < 4; p++)
                LDSM4(kb[p][0], kb[p][1], kb[p][2], kb[p][3], kAddr[p] + ks * 32);
#pragma unroll
            for (int p = 0; p < 4; p++) {
                MMA_TF32(sacc[2 * p],     qf[ks][0], qf[ks][1], qf[ks][2], qf[ks][3],
                         kb[p][0], kb[p][1]);
                MMA_TF32(sacc[2 * p + 1], qf[ks][0], qf[ks][1], qf[ks][2], qf[ks][3],
                         kb[p][2], kb[p][3]);
            }
        }

        // ---- online softmax ----
        const bool diag = (jb == qb);
        float mx0 = -1e30f, mx1 = -1e30f;
#pragma unroll
        for (int nt = 0; nt < 8; nt++) {
            float s0 = sacc[nt][0];
            float s1 = sacc[nt][1];
            float s2 = sacc[nt][2];
            float s3 = sacc[nt][3];
            if (diag) {
                int j = j0 + nt * 8 + q * 2;
                if (j     > r0)     s0 = -1e30f;
                if (j + 1 > r0)     s1 = -1e30f;
                if (j     > r0 + 8) s2 = -1e30f;
                if (j + 1 > r0 + 8) s3 = -1e30f;
            }
            sacc[nt][0] = s0; sacc[nt][1] = s1;
            sacc[nt][2] = s2; sacc[nt][3] = s3;
            mx0 = fmaxf(mx0, fmaxf(s0, s1));
            mx1 = fmaxf(mx1, fmaxf(s2, s3));
        }
        mx0 = fmaxf(mx0, __shfl_xor_sync(0xffffffffu, mx0, 1));
        mx0 = fmaxf(mx0, __shfl_xor_sync(0xffffffffu, mx0, 2));
        mx1 = fmaxf(mx1, __shfl_xor_sync(0xffffffffu, mx1, 1));
        mx1 = fmaxf(mx1, __shfl_xor_sync(0xffffffffu, mx1, 2));
        float mn0 = fmaxf(m0, mx0), mn1 = fmaxf(m1, mx1);
        float al0 = __expf(m0 - mn0), al1 = __expf(m1 - mn1);
        m0 = mn0; m1 = mn1;
        float ps0 = 0.f, ps1 = 0.f;
#pragma unroll
        for (int nt = 0; nt < 8; nt++) {
            float p0 = __expf(sacc[nt][0] - mn0);
            float p1 = __expf(sacc[nt][1] - mn0);
            float p2 = __expf(sacc[nt][2] - mn1);
            float p3 = __expf(sacc[nt][3] - mn1);
            ps0 += p0 + p1;
            ps1 += p2 + p3;
            sacc[nt][0] = p0; sacc[nt][1] = p1;
            sacc[nt][2] = p2; sacc[nt][3] = p3;
        }
        l0 = l0 * al0 + ps0;
        l1 = l1 * al1 + ps1;
#pragma unroll
        for (int nt = 0; nt < 8; nt++) {
            oacc[nt][0] *= al0; oacc[nt][1] *= al0;
            oacc[nt][2] *= al1; oacc[nt][3] *= al1;
        }

        __syncthreads();   // all warps done reading K before P overlay

        // ---- write P (tf32) into this warp's Ksm slice ----
        uint32_t* Psm = Ksm + wm * KST;
#pragma unroll
        for (int nt = 0; nt < 8; nt++) {
            *(uint2*)&Psm[grp * KST + nt * 8 + q * 2] =
                make_uint2(f2tf32(sacc[nt][0]), f2tf32(sacc[nt][1]));
            *(uint2*)&Psm[(grp + 8) * KST + nt * 8 + q * 2] =
                make_uint2(f2tf32(sacc[nt][2]), f2tf32(sacc[nt][3]));
        }
        __syncwarp();

        // ---- O += P V (LDSM frags) ----
#pragma unroll
        for (int ks = 0; ks < 8; ks++) {
            uint32_t af[4];
            LDSM4(af[0], af[1], af[2], af[3], pAddr + ks * 32);
            uint32_t vb[4][4];
#pragma unroll
            for (int p = 0; p < 4; p++)
                LDSM4(vb[p][0], vb[p][1], vb[p][2], vb[p][3], vAddr[p] + ks * 32);
#pragma unroll
            for (int p = 0; p < 4; p++) {
                MMA_TF32(oacc[2 * p],     af[0], af[1], af[2], af[3], vb[p][0], vb[p][1]);
                MMA_TF32(oacc[2 * p + 1], af[0], af[1], af[2], af[3], vb[p][2], vb[p][3]);
            }
        }
        __syncthreads();
    }

    l0 += __shfl_xor_sync(0xffffffffu, l0, 1);
    l0 += __shfl_xor_sync(0xffffffffu, l0, 2);
    l1 += __shfl_xor_sync(0xffffffffu, l1, 1);
    l1 += __shfl_xor_sync(0xffffffffu, l1, 2);
    const float inv0 = 1.f / l0;
    const float inv1 = 1.f / l1;

#pragma unroll
    for (int nt = 0; nt < 8; nt++) {
        int col = nt * 8 + q * 2;
        uint2 w0 = make_uint2(f2tf32(oacc[nt][0] * inv0), f2tf32(oacc[nt][1] * inv0));
        uint2 w1 = make_uint2(f2tf32(oacc[nt][2] * inv1), f2tf32(oacc[nt][3] * inv1));
        *(uint2*)(Og + base + (size_t)r0 * DD + col) = w0;
        *(uint2*)(Og + base + (size_t)(r0 + 8) * DD + col) = w1;
    }
}

// ---------------------------------------------------------------------------
extern "C" void kernel_launch(void* const* d_in, const int* in_sizes, int n_in,
                              void* d_out, int out_size)
{
    (void)in_sizes; (void)n_in; (void)out_size;
    const float* x  = (const float*)d_in[0];
    const float* wq = (const float*)d_in[2];
    const float* bq = (const float*)d_in[3];
    const float* wk = (const float*)d_in[4];
    const float* bk = (const float*)d_in[5];
    const float* wv = (const float*)d_in[6];
    const float* bv = (const float*)d_in[7];
    const float* wo = (const float*)d_in[8];
    const float* bo = (const float*)d_in[9];
    float* out = (float*)d_out;

    float *We, *X, *Qb, *Kb, *Vb, *Vt, *Ob;
    cudaGetSymbolAddress((void**)&We, g_We);
    cudaGetSymbolAddress((void**)&X,  g_X);
    cudaGetSymbolAddress((void**)&Qb, g_Q);
    cudaGetSymbolAddress((void**)&Kb, g_K);
    cudaGetSymbolAddress((void**)&Vb, g_V);
    cudaGetSymbolAddress((void**)&Vt, g_Vt);
    cudaGetSymbolAddress((void**)&Ob, g_O);

    cudaFuncSetAttribute(gemm_tf32<true>,
                         cudaFuncAttributeMaxDynamicSharedMemorySize, GEMM_SMEM);
    cudaFuncSetAttribute(gemm_tf32<false>,
                         cudaFuncAttributeMaxDynamicSharedMemorySize, GEMM_SMEM);

    expand_kernel<<<dim3(DD * DD / 256, 4), 256>>>(wq, wk, wv, wo);
    convert_x<<<MM * DD / 1024, 256>>>(x);

    // QKV projections: outputs tf32-rounded (flash re-rounds anyway -> exact)
    gemm_tf32<true><<<dim3(DD / 128, MM / 128, 3), 256, GEMM_SMEM>>>(
        X, We, We + DD * DD, We + 2 * DD * DD, bq, bk, bv, Qb, Kb, Vb);

    transpose_v<<<dim3(32, 32, 2), dim3(32, 8)>>>();

    flash_mma<<<dim3(32, 16), 128>>>(Qb, Kb, Vt, Ob);

    // Output projection: full fp32 output
    gemm_tf32<false><<<dim3(DD / 128, MM / 128, 1), 256, GEMM_SMEM>>>(
        Ob, We + 3 * DD * DD, We + 3 * DD * DD, We + 3 * DD * DD,
        bo, bo, bo, out, out, out);
}

// round 16
// speedup vs baseline: 1.0937x; 1.0125x over previous
#include <cuda_runtime.h>
#include <cstdint>

// ---------------------------------------------------------------------------
// B=2, N=1024, D=1024, K=8 (circulant), H=16, dh=64
// All GEMM/flash operands pre-rounded to tf32 in gmem => no cvt in hot loops.
// Weights expanded TRANSPOSED: Wt[n][k] = W[k][n]  (k contiguous)
// V is produced directly TRANSPOSED by the QKV GEMM: Vt[b][col][seq]
// ---------------------------------------------------------------------------
constexpr int DD = 1024;
constexpr int MM = 2048;

__device__ float g_We[4][DD * DD];   // expanded weights (tf32-rounded), Wt[n][k]
__device__ float g_X[MM * DD];       // x, tf32-rounded
__device__ float g_Q[MM * DD];       // tf32-rounded
__device__ float g_K[MM * DD];       // tf32-rounded
__device__ float g_Vt[MM * DD];      // V transposed per batch, tf32-rounded
__device__ float g_O[MM * DD];       // attention out, tf32-rounded

__device__ __forceinline__ uint32_t f2tf32(float f) {
    uint32_t r;
    asm("cvt.rna.tf32.f32 %0, %1;" : "=r"(r) : "f"(f));
    return r;
}

#define MMA_TF32(ACC, A0, A1, A2, A3, B0, B1)                            \
    asm volatile(                                                        \
        "mma.sync.aligned.m16n8k8.row.col.f32.tf32.tf32.f32 "            \
        "{%0,%1,%2,%3}, {%4,%5,%6,%7}, {%8,%9}, {%0,%1,%2,%3};"          \
        : "+f"((ACC)[0]), "+f"((ACC)[1]), "+f"((ACC)[2]), "+f"((ACC)[3]) \
        : "r"(A0), "r"(A1), "r"(A2), "r"(A3), "r"(B0), "r"(B1))

#define LDSM4(R0, R1, R2, R3, ADDR)                                      \
    asm volatile("ldmatrix.sync.aligned.m8n8.x4.shared.b16 "             \
                 "{%0,%1,%2,%3}, [%4];"                                  \
                 : "=r"(R0), "=r"(R1), "=r"(R2), "=r"(R3) : "r"(ADDR))

__device__ __forceinline__ void cp16(uint32_t smem, const void* g) {
    asm volatile("cp.async.ca.shared.global [%0], [%1], 16;\n"
                 :: "r"(smem), "l"(g));
}

extern __shared__ uint32_t dynsm[];

// ---------------------------------------------------------------------------
// Prep: expand circulant weights (y=0..3) + tf32-round x (y=4,5)
// ---------------------------------------------------------------------------
__global__ void prep_kernel(const float* __restrict__ w0,
                            const float* __restrict__ w1,
                            const float* __restrict__ w2,
                            const float* __restrict__ w3,
                            const float* __restrict__ x)
{
    int idx = blockIdx.x * 256 + threadIdx.x;       // 0 .. 2^20-1
    int y = blockIdx.y;
    if (y < 4) {
        const float* w;
        switch (y) {
            case 0:  w = w0; break;
            case 1:  w = w1; break;
            case 2:  w = w2; break;
            default: w = w3; break;
        }
        int n = idx >> 10;
        int k = idx & 1023;
        g_We[y][idx] = __uint_as_float(
            f2tf32(w[((n >> 3) << 10) + ((k >> 3) << 3) + ((n - k) & 7)]));
    } else {
        int base = (y - 4) * (1 << 20);
        g_X[base + idx] = __uint_as_float(f2tf32(x[base + idx]));
    }
}

// ---------------------------------------------------------------------------
// TF32 GEMM + bias: 128x128 tile, BK=16, 8 warps of 32x64, ldmatrix frags,
// 4-stage cp.async pipeline, ONE barrier per iteration.
// ROUND: tf32-round outputs. VTZ: blockIdx.z whose output is stored
// TRANSPOSED per batch (V -> Vt[b][col][seq]); -1 = none.
// ---------------------------------------------------------------------------
constexpr int GST  = 20;
constexpr int BUFW = 128 * GST;
constexpr int NST  = 4;
constexpr int GEMM_SMEM = 2 * NST * BUFW * 4;   // 81920 bytes

template <bool ROUND, int VTZ>
__global__ __launch_bounds__(256, 2)
void gemm_tf32(const float* __restrict__ A,
               const float* __restrict__ B0, const float* __restrict__ B1,
               const float* __restrict__ B2,
               const float* __restrict__ bi0, const float* __restrict__ bi1,
               const float* __restrict__ bi2,
               float* __restrict__ C0, float* __restrict__ C1,
               float* __restrict__ C2)
{
    const float* Bm; const float* bias; float* C;
    if (blockIdx.z == 0)      { Bm = B0; bias = bi0; C = C0; }
    else if (blockIdx.z == 1) { Bm = B1; bias = bi1; C = C1; }
    else                      { Bm = B2; bias = bi2; C = C2; }

    const int tid  = threadIdx.x;
    const int warp = tid >> 5;
    const int lane = tid & 31;
    const int grp  = lane >> 2;
    const int q    = lane & 3;

    const int cRow = blockIdx.y * 128;
    const int cCol = blockIdx.x * 128;
    const int wm   = (warp & 3) * 32;
    const int wn   = (warp >> 2) * 64;

    const int sr = tid >> 2;
    const int sc = (tid & 3) * 4;

    const float* Ap = A  + (size_t)(cRow + sr) * DD + sc;
    const float* Bp = Bm + (size_t)(cCol + sr) * DD + sc;

    const uint32_t aBase = (uint32_t)__cvta_generic_to_shared(dynsm);
    const uint32_t bBase = aBase + NST * BUFW * 4;

    const uint32_t sA0 = aBase + (sr * GST + sc) * 4;
    const uint32_t sA1 = sA0 + 64 * GST * 4;
    const uint32_t sB0 = bBase + (sr * GST + sc) * 4;
    const uint32_t sB1 = sB0 + 64 * GST * 4;

    uint32_t aAddr[2];
#pragma unroll
    for (int mi = 0; mi < 2; mi++)
        aAddr[mi] = aBase + ((wm + mi * 16 + (lane & 15)) * GST) * 4 +
                    (lane >> 4) * 16;
    uint32_t bAddr[4];
#pragma unroll
    for (int p = 0; p < 4; p++)
        bAddr[p] = bBase + ((wn + (2 * p + (lane >> 4)) * 8 + (lane & 7)) * GST) * 4 +
                   ((lane >> 3) & 1) * 16;

    float acc[2][8][4];
#pragma unroll
    for (int mi = 0; mi < 2; mi++)
#pragma unroll
        for (int ni = 0; ni < 8; ni++)
#pragma unroll
            for (int c = 0; c < 4; c++) acc[mi][ni][c] = 0.f;

    auto issue_stage = [&](int s, int kb) {
        const uint32_t so = (uint32_t)s * (BUFW * 4);
        cp16(sA0 + so, Ap + kb);
        cp16(sA1 + so, Ap + 64 * DD + kb);
        cp16(sB0 + so, Bp + kb);
        cp16(sB1 + so, Bp + 64 * DD + kb);
        asm volatile("cp.async.commit_group;");
    };

    auto compute = [&](int it) {
        const uint32_t so = (uint32_t)(it & 3) * (BUFW * 4);
#pragma unroll
        for (int kc = 0; kc < 2; kc++) {
            const uint32_t ko = so + kc * 32;
            uint32_t a0[4], a1[4];
            LDSM4(a0[0], a0[1], a0[2], a0[3], aAddr[0] + ko);
            LDSM4(a1[0], a1[1], a1[2], a1[3], aAddr[1] + ko);
            uint32_t bv[4][4];
#pragma unroll
            for (int p = 0; p < 4; p++)
                LDSM4(bv[p][0], bv[p][1], bv[p][2], bv[p][3], bAddr[p] + ko);
#pragma unroll
            for (int p = 0; p < 4; p++) {
                MMA_TF32(acc[0][2 * p],     a0[0], a0[1], a0[2], a0[3], bv[p][0], bv[p][1]);
                MMA_TF32(acc[0][2 * p + 1], a0[0], a0[1], a0[2], a0[3], bv[p][2], bv[p][3]);
                MMA_TF32(acc[1][2 * p],     a1[0], a1[1], a1[2], a1[3], bv[p][0], bv[p][1]);
                MMA_TF32(acc[1][2 * p + 1], a1[0], a1[1], a1[2], a1[3], bv[p][2], bv[p][3]);
            }
        }
    };

    issue_stage(0, 0);
    issue_stage(1, 16);
    issue_stage(2, 32);

    for (int it = 0; it <= 60; it++) {
        asm volatile("cp.async.wait_group 2;");
        __syncthreads();
        issue_stage((it + 3) & 3, (it + 3) * 16);
        compute(it);
    }
    asm volatile("cp.async.wait_group 2;");
    __syncthreads();
    compute(61);
    asm volatile("cp.async.wait_group 1;");
    __syncthreads();
    compute(62);
    asm volatile("cp.async.wait_group 0;");
    __syncthreads();
    compute(63);

#pragma unroll
    for (int mi = 0; mi < 2; mi++) {
#pragma unroll
        for (int ni = 0; ni < 8; ni++) {
            int row = cRow + wm + mi * 16 + grp;
            int col = cCol + wn + ni * 8 + q * 2;
            float bx = bias[col], by = bias[col + 1];
            float v0 = acc[mi][ni][0] + bx, v1 = acc[mi][ni][1] + by;
            float v2 = acc[mi][ni][2] + bx, v3 = acc[mi][ni][3] + by;
            if (ROUND) {
                v0 = __uint_as_float(f2tf32(v0));
                v1 = __uint_as_float(f2tf32(v1));
                v2 = __uint_as_float(f2tf32(v2));
                v3 = __uint_as_float(f2tf32(v3));
            }
            if (VTZ >= 0 && blockIdx.z == VTZ) {
                // transposed per batch: dst[b][col][seq]
                size_t bb  = ((size_t)(row >> 10)) << 20;
                int seq = row & 1023;
                C[bb + (size_t)col * 1024 + seq]           = v0;
                C[bb + (size_t)(col + 1) * 1024 + seq]     = v1;
                C[bb + (size_t)col * 1024 + seq + 8]       = v2;
                C[bb + (size_t)(col + 1) * 1024 + seq + 8] = v3;
            } else {
                *(float2*)(C + (size_t)row * DD + col)       = make_float2(v0, v1);
                *(float2*)(C + (size_t)(row + 8) * DD + col) = make_float2(v2, v3);
            }
        }
    }
}

// ---------------------------------------------------------------------------
// Tensor-core causal flash attention. Pure-copy staging (inputs tf32).
// Dynamic smem: Ksm | Vsm | Psm, each 64*68 words. P is per-warp private
// => only TWO __syncthreads per KV tile.
// ---------------------------------------------------------------------------
constexpr int FST  = 68;
constexpr int FBUF = 64 * FST;
constexpr int FLASH_SMEM = 3 * FBUF * 4;   // 52224 bytes

__global__ __launch_bounds__(128, 3)
void flash_mma(const float* __restrict__ Qg, const float* __restrict__ Kg,
               const float* __restrict__ Vtg, float* __restrict__ Og)
{
    const int tid  = threadIdx.x;
    const int warp = tid >> 5;
    const int lane = tid & 31;
    const int grp  = lane >> 2;
    const int q    = lane & 3;

    const int qb = 15 - blockIdx.y;
    const int i0 = qb * 64;
    const int h  = blockIdx.x & 15;
    const int b  = blockIdx.x >> 4;
    const size_t base   = (size_t)b * (1024 * 1024) + h * 64;
    const size_t vtbase = (size_t)b * (1024 * 1024) + (size_t)(h * 64) * 1024;

    const int wm = warp * 16;
    const int r0 = i0 + wm + grp;

    uint32_t* Ksm = dynsm;
    uint32_t* Vsm = dynsm + FBUF;
    uint32_t* Psm = dynsm + 2 * FBUF;

    const uint32_t kBase = (uint32_t)__cvta_generic_to_shared(Ksm);
    const uint32_t vBase = (uint32_t)__cvta_generic_to_shared(Vsm);
    const uint32_t pBase = (uint32_t)__cvta_generic_to_shared(Psm);
    uint32_t kAddr[4], vAddr[4];
#pragma unroll
    for (int p = 0; p < 4; p++) {
        int nr = (2 * p + (lane >> 4)) * 8 + (lane & 7);
        kAddr[p] = kBase + nr * FST * 4 + ((lane >> 3) & 1) * 16;
        vAddr[p] = vBase + nr * FST * 4 + ((lane >> 3) & 1) * 16;
    }
    const uint32_t pAddr = pBase + (wm + (lane & 15)) * FST * 4 + (lane >> 4) * 16;
    uint32_t* Pw = Psm + wm * FST;

    // ---- stage Q tile into Vsm (pure copy), pull A-frags ----
#pragma unroll
    for (int it = 0; it < 8; it++) {
        int idx = tid + it * 128;
        int row = idx >> 4;
        int c4  = (idx & 15) << 2;
        *(float4*)&((float*)Vsm)[row * FST + c4] =
            *(const float4*)(Qg + base + (size_t)(i0 + row) * DD + c4);
    }
    __syncthreads();
    uint32_t qf[8][4];
    {
        const float* Qs = (const float*)Vsm;
#pragma unroll
        for (int ks = 0; ks < 8; ks++) {
            qf[ks][0] = f2tf32(Qs[(wm + grp)     * FST + ks * 8 + q] * 0.125f);
            qf[ks][1] = f2tf32(Qs[(wm + grp + 8) * FST + ks * 8 + q] * 0.125f);
            qf[ks][2] = f2tf32(Qs[(wm + grp)     * FST + ks * 8 + q + 4] * 0.125f);
            qf[ks][3] = f2tf32(Qs[(wm + grp + 8) * FST + ks * 8 + q + 4] * 0.125f);
        }
    }
    __syncthreads();

    float oacc[8][4];
#pragma unroll
    for (int nt = 0; nt < 8; nt++)
#pragma unroll
        for (int c = 0; c < 4; c++) oacc[nt][c] = 0.f;
    float m0 = -1e30f, m1 = -1e30f, l0 = 0.f, l1 = 0.f;

    for (int jb = 0; jb <= qb; jb++) {
        const int j0 = jb * 64;

        // ---- stage K natural, Vt natural: pure uint4 copies ----
#pragma unroll
        for (int it = 0; it < 8; it++) {
            int idx = tid + it * 128;
            int row = idx >> 4;
            int c4  = (idx & 15) << 2;
            *(uint4*)&Ksm[row * FST + c4] =
                *(const uint4*)(Kg + base + (size_t)(j0 + row) * DD + c4);
            *(uint4*)&Vsm[row * FST + c4] =
                *(const uint4*)(Vtg + vtbase + (size_t)row * 1024 + j0 + c4);
        }
        __syncthreads();                         // barrier 1: tiles ready

        // ---- S = (Q/8) K^T ----
        float sacc[8][4];
#pragma unroll
        for (int nt = 0; nt < 8; nt++)
#pragma unroll
            for (int c = 0; c < 4; c++) sacc[nt][c] = 0.f;
#pragma unroll
        for (int ks = 0; ks < 8; ks++) {
            uint32_t kb[4][4];
#pragma unroll
            for (int p = 0; p < 4; p++)
                LDSM4(kb[p][0], kb[p][1], kb[p][2], kb[p][3], kAddr[p] + ks * 32);
#pragma unroll
            for (int p = 0; p < 4; p++) {
                MMA_TF32(sacc[2 * p],     qf[ks][0], qf[ks][1], qf[ks][2], qf[ks][3],
                         kb[p][0], kb[p][1]);
                MMA_TF32(sacc[2 * p + 1], qf[ks][0], qf[ks][1], qf[ks][2], qf[ks][3],
                         kb[p][2], kb[p][3]);
            }
        }

        // ---- online softmax ----
        const bool diag = (jb == qb);
        float mx0 = -1e30f, mx1 = -1e30f;
#pragma unroll
        for (int nt = 0; nt < 8; nt++) {
            float s0 = sacc[nt][0];
            float s1 = sacc[nt][1];
            float s2 = sacc[nt][2];
            float s3 = sacc[nt][3];
            if (diag) {
                int j = j0 + nt * 8 + q * 2;
                if (j     > r0)     s0 = -1e30f;
                if (j + 1 > r0)     s1 = -1e30f;
                if (j     > r0 + 8) s2 = -1e30f;
                if (j + 1 > r0 + 8) s3 = -1e30f;
            }
            sacc[nt][0] = s0; sacc[nt][1] = s1;
            sacc[nt][2] = s2; sacc[nt][3] = s3;
            mx0 = fmaxf(mx0, fmaxf(s0, s1));
            mx1 = fmaxf(mx1, fmaxf(s2, s3));
        }
        mx0 = fmaxf(mx0, __shfl_xor_sync(0xffffffffu, mx0, 1));
        mx0 = fmaxf(mx0, __shfl_xor_sync(0xffffffffu, mx0, 2));
        mx1 = fmaxf(mx1, __shfl_xor_sync(0xffffffffu, mx1, 1));
        mx1 = fmaxf(mx1, __shfl_xor_sync(0xffffffffu, mx1, 2));
        float mn0 = fmaxf(m0, mx0), mn1 = fmaxf(m1, mx1);
        float al0 = __expf(m0 - mn0), al1 = __expf(m1 - mn1);
        m0 = mn0; m1 = mn1;
        float ps0 = 0.f, ps1 = 0.f;
#pragma unroll
        for (int nt = 0; nt < 8; nt++) {
            float p0 = __expf(sacc[nt][0] - mn0);
            float p1 = __expf(sacc[nt][1] - mn0);
            float p2 = __expf(sacc[nt][2] - mn1);
            float p3 = __expf(sacc[nt][3] - mn1);
            ps0 += p0 + p1;
            ps1 += p2 + p3;
            sacc[nt][0] = p0; sacc[nt][1] = p1;
            sacc[nt][2] = p2; sacc[nt][3] = p3;
        }
        l0 = l0 * al0 + ps0;
        l1 = l1 * al1 + ps1;
#pragma unroll
        for (int nt = 0; nt < 8; nt++) {
            oacc[nt][0] *= al0; oacc[nt][1] *= al0;
            oacc[nt][2] *= al1; oacc[nt][3] *= al1;
        }

        // ---- write P to this warp's PRIVATE Psm slice (no CTA barrier) ----
#pragma unroll
        for (int nt = 0; nt < 8; nt++) {
            *(uint2*)&Pw[grp * FST + nt * 8 + q * 2] =
                make_uint2(f2tf32(sacc[nt][0]), f2tf32(sacc[nt][1]));
            *(uint2*)&Pw[(grp + 8) * FST + nt * 8 + q * 2] =
                make_uint2(f2tf32(sacc[nt][2]), f2tf32(sacc[nt][3]));
        }
        __syncwarp();

        // ---- O += P V (LDSM frags) ----
#pragma unroll
        for (int ks = 0; ks < 8; ks++) {
            uint32_t af[4];
            LDSM4(af[0], af[1], af[2], af[3], pAddr + ks * 32);
            uint32_t vb[4][4];
#pragma unroll
            for (int p = 0; p < 4; p++)
                LDSM4(vb[p][0], vb[p][1], vb[p][2], vb[p][3], vAddr[p] + ks * 32);
#pragma unroll
            for (int p = 0; p < 4; p++) {
                MMA_TF32(oacc[2 * p],     af[0], af[1], af[2], af[3], vb[p][0], vb[p][1]);
                MMA_TF32(oacc[2 * p + 1], af[0], af[1], af[2], af[3], vb[p][2], vb[p][3]);
            }
        }
        __syncthreads();                         // barrier 2: K/V reusable
    }

    l0 += __shfl_xor_sync(0xffffffffu, l0, 1);
    l0 += __shfl_xor_sync(0xffffffffu, l0, 2);
    l1 += __shfl_xor_sync(0xffffffffu, l1, 1);
    l1 += __shfl_xor_sync(0xffffffffu, l1, 2);
    const float inv0 = 1.f / l0;
    const float inv1 = 1.f / l1;

#pragma unroll
    for (int nt = 0; nt < 8; nt++) {
        int col = nt * 8 + q * 2;
        uint2 w0 = make_uint2(f2tf32(oacc[nt][0] * inv0), f2tf32(oacc[nt][1] * inv0));
        uint2 w1 = make_uint2(f2tf32(oacc[nt][2] * inv1), f2tf32(oacc[nt][3] * inv1));
        *(uint2*)(Og + base + (size_t)r0 * DD + col) = w0;
        *(uint2*)(Og + base + (size_t)(r0 + 8) * DD + col) = w1;
    }
}

// ---------------------------------------------------------------------------
extern "C" void kernel_launch(void* const* d_in, const int* in_sizes, int n_in,
                              void* d_out, int out_size)
{
    (void)in_sizes; (void)n_in; (void)out_size;
    const float* x  = (const float*)d_in[0];
    const float* wq = (const float*)d_in[2];
    const float* bq = (const float*)d_in[3];
    const float* wk = (const float*)d_in[4];
    const float* bk = (const float*)d_in[5];
    const float* wv = (const float*)d_in[6];
    const float* bv = (const float*)d_in[7];
    const float* wo = (const float*)d_in[8];
    const float* bo = (const float*)d_in[9];
    float* out = (float*)d_out;

    float *We, *X, *Qb, *Kb, *Vt, *Ob;
    cudaGetSymbolAddress((void**)&We, g_We);
    cudaGetSymbolAddress((void**)&X,  g_X);
    cudaGetSymbolAddress((void**)&Qb, g_Q);
    cudaGetSymbolAddress((void**)&Kb, g_K);
    cudaGetSymbolAddress((void**)&Vt, g_Vt);
    cudaGetSymbolAddress((void**)&Ob, g_O);

    cudaFuncSetAttribute(gemm_tf32<true, 2>,
                         cudaFuncAttributeMaxDynamicSharedMemorySize, GEMM_SMEM);
    cudaFuncSetAttribute(gemm_tf32<false, -1>,
                         cudaFuncAttributeMaxDynamicSharedMemorySize, GEMM_SMEM);
    cudaFuncSetAttribute(flash_mma,
                         cudaFuncAttributeMaxDynamicSharedMemorySize, FLASH_SMEM);

    prep_kernel<<<dim3(DD * DD / 256, 6), 256>>>(wq, wk, wv, wo, x);

    // QKV projections; z==2 (V) written transposed into g_Vt
    gemm_tf32<true, 2><<<dim3(DD / 128, MM / 128, 3), 256, GEMM_SMEM>>>(
        X, We, We + DD * DD, We + 2 * DD * DD, bq, bk, bv, Qb, Kb, Vt);

    flash_mma<<<dim3(32, 16), 128, FLASH_SMEM>>>(Qb, Kb, Vt, Ob);

    gemm_tf32<false, -1><<<dim3(DD / 128, MM / 128, 1), 256, GEMM_SMEM>>>(
        Ob, We + 3 * DD * DD, We + 3 * DD * DD, We + 3 * DD * DD,
        bo, bo, bo, out, out, out);
}